// round 3
// baseline (speedup 1.0000x reference)
#include <cuda_runtime.h>
#include <cstdint>

// out[b,s,:] = x[b,s,:] + combined[s,:], combined from 3 PE tables + segment searches.
// x: [8, 16384, 512] fp32 -> 256 MiB read + 256 MiB write. Pure HBM streaming.
// Strategy: one wave of persistent-ish blocks, grid-stride over s; comb computed
// once per s and reused across the fully unrolled batch loop; streaming hints
// on the big x/out streams.

#define B_CONST 8
#define D4 128            // D/4 = 512/4
#define MAX_PIXELS 900

__global__ __launch_bounds__(128)
void pe_add_kernel(const float4* __restrict__ x,
                   const float4* __restrict__ pix_pe,
                   const float4* __restrict__ grd_pe,
                   const float4* __restrict__ pr_pe,
                   const int*    __restrict__ g_starts,
                   const int*    __restrict__ g_lens,
                   const int*    __restrict__ p_starts,
                   const int*    __restrict__ p_lens,
                   int n_grids, int n_pairs, int n_pairs_pe_rows,
                   int S,
                   float4* __restrict__ out)
{
    const int t = threadIdx.x;                 // 0..127 -> float4 lane over D
    const size_t bstride = (size_t)S * D4;

    for (int s = blockIdx.x; s < S; s += gridDim.x) {
        // ---- searchsorted(grid_starts, s, 'right') - 1 ----
        int lo = 0, hi = n_grids;
        while (lo < hi) {
            int mid = (lo + hi) >> 1;
            if (g_starts[mid] <= s) lo = mid + 1; else hi = mid;
        }
        const int gid  = lo - 1;
        const int goff = s - g_starts[gid];
        const bool gmask = (goff < g_lens[gid]);
        int goffc = goff; if (goffc < 0) goffc = 0; if (goffc > MAX_PIXELS - 1) goffc = MAX_PIXELS - 1;

        // ---- searchsorted(pair_starts, s, 'right') - 1 ----
        lo = 0; hi = n_pairs;
        while (lo < hi) {
            int mid = (lo + hi) >> 1;
            if (p_starts[mid] <= s) lo = mid + 1; else hi = mid;
        }
        const int pid  = lo - 1;
        const int poff = s - p_starts[pid];
        const bool pmask = (poff < p_lens[pid]);
        int pidc = pid; if (pidc < 0) pidc = 0; if (pidc > n_pairs_pe_rows - 1) pidc = n_pairs_pe_rows - 1;

        // ---- combined[s, t*4..t*4+3] (PE tables stay resident in L1/L2) ----
        float4 comb = make_float4(0.f, 0.f, 0.f, 0.f);
        if (gmask) {
            float4 a = __ldg(&pix_pe[(size_t)goffc * D4 + t]);
            float4 b = __ldg(&grd_pe[(size_t)(gid & 1) * D4 + t]);
            comb.x = a.x + b.x; comb.y = a.y + b.y; comb.z = a.z + b.z; comb.w = a.w + b.w;
        }
        if (pmask) {
            float4 c = __ldg(&pr_pe[(size_t)pidc * D4 + t]);
            comb.x += c.x; comb.y += c.y; comb.z += c.z; comb.w += c.w;
        }

        // ---- streaming add across all 8 batches, fully unrolled for MLP ----
        const size_t row = (size_t)s * D4 + t;
        float4 v[B_CONST];
#pragma unroll
        for (int b = 0; b < B_CONST; ++b)
            v[b] = __ldcs(&x[row + (size_t)b * bstride]);
#pragma unroll
        for (int b = 0; b < B_CONST; ++b) {
            v[b].x += comb.x; v[b].y += comb.y; v[b].z += comb.z; v[b].w += comb.w;
            __stcs(&out[row + (size_t)b * bstride], v[b]);
        }
    }
}

extern "C" void kernel_launch(void* const* d_in, const int* in_sizes, int n_in,
                              void* d_out, int out_size)
{
    const float* x        = (const float*)d_in[0];
    const float* pix_pe   = (const float*)d_in[1];
    const float* grd_pe   = (const float*)d_in[2];
    const float* pr_pe    = (const float*)d_in[3];
    const int*   g_starts = (const int*)d_in[4];
    const int*   g_lens   = (const int*)d_in[5];
    const int*   p_starts = (const int*)d_in[6];
    const int*   p_lens   = (const int*)d_in[7];

    const int D = in_sizes[2] / 2;            // grids_pe is [2, D]
    const int n_grids = in_sizes[4];
    const int n_pairs = in_sizes[6];
    const int n_pairs_pe_rows = in_sizes[3] / D;
    const int S = out_size / (B_CONST * D);   // 16384

    // ~one full wave at expected occupancy (148 SMs x ~9 blocks); grid-stride
    // covers the remainder without multi-wave churn.
    int grid = 148 * 12;
    if (grid > S) grid = S;

    pe_add_kernel<<<grid, 128>>>(
        (const float4*)x, (const float4*)pix_pe, (const float4*)grd_pe, (const float4*)pr_pe,
        g_starts, g_lens, p_starts, p_lens,
        n_grids, n_pairs, n_pairs_pe_rows, S,
        (float4*)d_out);
}

// round 5
// speedup vs baseline: 1.1170x; 1.1170x over previous
#include <cuda_runtime.h>
#include <cstdint>

// out[b,s,:] = x[b,s,:] + combined[s,:]  (combined batch-invariant, from 3 PE tables)
// x: [8, 16384, 512] fp32 -> 256 MiB read + 256 MiB write, pure HBM streaming.
// Shape: one block per s-position (16384 blocks x 128 threads), comb computed once
// per s in registers, all 8 batch loads front-batched for max MLP.

#define B_CONST 8
#define D4 128            // D/4 = 512/4
#define MAX_PIXELS 900

__global__ __launch_bounds__(128)
void pe_add_kernel(const float4* __restrict__ x,
                   const float4* __restrict__ pix_pe,
                   const float4* __restrict__ grd_pe,
                   const float4* __restrict__ pr_pe,
                   const int*    __restrict__ g_starts,
                   const int*    __restrict__ g_lens,
                   const int*    __restrict__ p_starts,
                   const int*    __restrict__ p_lens,
                   int n_grids, int n_pairs, int n_pairs_pe_rows,
                   int S,
                   float4* __restrict__ out)
{
    const int s = blockIdx.x;
    const int t = threadIdx.x;   // 0..127 -> float4 lane over D

    // ---- searchsorted(grid_starts, s, 'right') - 1 ----
    int lo = 0, hi = n_grids;
    while (lo < hi) {
        int mid = (lo + hi) >> 1;
        if (g_starts[mid] <= s) lo = mid + 1; else hi = mid;
    }
    const int gid  = lo - 1;
    const int goff = s - g_starts[gid];
    const bool gmask = (goff < g_lens[gid]);
    int goffc = goff; if (goffc < 0) goffc = 0; if (goffc > MAX_PIXELS - 1) goffc = MAX_PIXELS - 1;

    // ---- searchsorted(pair_starts, s, 'right') - 1 ----
    lo = 0; hi = n_pairs;
    while (lo < hi) {
        int mid = (lo + hi) >> 1;
        if (p_starts[mid] <= s) lo = mid + 1; else hi = mid;
    }
    const int pid  = lo - 1;
    const int poff = s - p_starts[pid];
    const bool pmask = (poff < p_lens[pid]);
    int pidc = pid; if (pidc < 0) pidc = 0; if (pidc > n_pairs_pe_rows - 1) pidc = n_pairs_pe_rows - 1;

    // ---- combined[s, t*4..t*4+3] in registers (PE tables resident in L1/L2) ----
    float4 comb = make_float4(0.f, 0.f, 0.f, 0.f);
    if (gmask) {
        float4 a = __ldg(&pix_pe[(size_t)goffc * D4 + t]);
        float4 b = __ldg(&grd_pe[(size_t)(gid & 1) * D4 + t]);
        comb.x = a.x + b.x; comb.y = a.y + b.y; comb.z = a.z + b.z; comb.w = a.w + b.w;
    }
    if (pmask) {
        float4 c = __ldg(&pr_pe[(size_t)pidc * D4 + t]);
        comb.x += c.x; comb.y += c.y; comb.z += c.z; comb.w += c.w;
    }

    // ---- front-batch all 8 batch loads (MLP=8), then add+store ----
    const size_t row = (size_t)s * D4 + t;
    const size_t bstride = (size_t)S * D4;
    float4 v[B_CONST];
#pragma unroll
    for (int b = 0; b < B_CONST; ++b)
        v[b] = x[row + (size_t)b * bstride];
#pragma unroll
    for (int b = 0; b < B_CONST; ++b) {
        v[b].x += comb.x; v[b].y += comb.y; v[b].z += comb.z; v[b].w += comb.w;
        out[row + (size_t)b * bstride] = v[b];
    }
}

extern "C" void kernel_launch(void* const* d_in, const int* in_sizes, int n_in,
                              void* d_out, int out_size)
{
    const float* x        = (const float*)d_in[0];
    const float* pix_pe   = (const float*)d_in[1];
    const float* grd_pe   = (const float*)d_in[2];
    const float* pr_pe    = (const float*)d_in[3];
    const int*   g_starts = (const int*)d_in[4];
    const int*   g_lens   = (const int*)d_in[5];
    const int*   p_starts = (const int*)d_in[6];
    const int*   p_lens   = (const int*)d_in[7];

    const int D = in_sizes[2] / 2;            // grids_pe is [2, D]
    const int n_grids = in_sizes[4];
    const int n_pairs = in_sizes[6];
    const int n_pairs_pe_rows = in_sizes[3] / D;
    const int S = out_size / (B_CONST * D);   // 16384

    pe_add_kernel<<<S, 128>>>(
        (const float4*)x, (const float4*)pix_pe, (const float4*)grd_pe, (const float4*)pr_pe,
        g_starts, g_lens, p_starts, p_lens,
        n_grids, n_pairs, n_pairs_pe_rows, S,
        (float4*)d_out);
}

// round 6
// speedup vs baseline: 1.1234x; 1.0057x over previous
#include <cuda_runtime.h>
#include <cstdint>

// out[b,s,:] = x[b,s,:] + combined[s,:]  (combined batch-invariant, from 3 PE tables)
// x: [8, 16384, 512] fp32 -> 256 MiB read + 256 MiB write, pure HBM streaming.
// Shape: one block per s-position (16384 blocks x 128 threads).
// Key ordering: issue all 8 x-loads FIRST, then do the (dependent, latency-heavy)
// segment searches + PE gathers while those loads are in flight, then add+store.

#define B_CONST 8
#define D4 128            // D/4 = 512/4
#define MAX_PIXELS 900

__global__ __launch_bounds__(128)
void pe_add_kernel(const float4* __restrict__ x,
                   const float4* __restrict__ pix_pe,
                   const float4* __restrict__ grd_pe,
                   const float4* __restrict__ pr_pe,
                   const int*    __restrict__ g_starts,
                   const int*    __restrict__ g_lens,
                   const int*    __restrict__ p_starts,
                   const int*    __restrict__ p_lens,
                   int n_grids, int n_pairs, int n_pairs_pe_rows,
                   int S,
                   float4* __restrict__ out)
{
    const int s = blockIdx.x;
    const int t = threadIdx.x;   // 0..127 -> float4 lane over D

    // ---- issue the big streaming loads first (independent of everything below) ----
    const size_t row = (size_t)s * D4 + t;
    const size_t bstride = (size_t)S * D4;
    float4 v[B_CONST];
#pragma unroll
    for (int b = 0; b < B_CONST; ++b)
        v[b] = x[row + (size_t)b * bstride];

    // ---- searchsorted(grid_starts, s, 'right') - 1 (overlapped with x loads) ----
    int lo = 0, hi = n_grids;
    while (lo < hi) {
        int mid = (lo + hi) >> 1;
        if (g_starts[mid] <= s) lo = mid + 1; else hi = mid;
    }
    const int gid  = lo - 1;
    const int goff = s - g_starts[gid];
    const bool gmask = (goff < g_lens[gid]);
    int goffc = goff; if (goffc < 0) goffc = 0; if (goffc > MAX_PIXELS - 1) goffc = MAX_PIXELS - 1;

    // ---- searchsorted(pair_starts, s, 'right') - 1 ----
    lo = 0; hi = n_pairs;
    while (lo < hi) {
        int mid = (lo + hi) >> 1;
        if (p_starts[mid] <= s) lo = mid + 1; else hi = mid;
    }
    const int pid  = lo - 1;
    const int poff = s - p_starts[pid];
    const bool pmask = (poff < p_lens[pid]);
    int pidc = pid; if (pidc < 0) pidc = 0; if (pidc > n_pairs_pe_rows - 1) pidc = n_pairs_pe_rows - 1;

    // ---- combined[s, t*4..t*4+3] in registers (PE tables resident in L1/L2) ----
    float4 comb = make_float4(0.f, 0.f, 0.f, 0.f);
    if (gmask) {
        float4 a = __ldg(&pix_pe[(size_t)goffc * D4 + t]);
        float4 b = __ldg(&grd_pe[(size_t)(gid & 1) * D4 + t]);
        comb.x = a.x + b.x; comb.y = a.y + b.y; comb.z = a.z + b.z; comb.w = a.w + b.w;
    }
    if (pmask) {
        float4 c = __ldg(&pr_pe[(size_t)pidc * D4 + t]);
        comb.x += c.x; comb.y += c.y; comb.z += c.z; comb.w += c.w;
    }

    // ---- add + streaming stores (touch-once -> evict-first) ----
#pragma unroll
    for (int b = 0; b < B_CONST; ++b) {
        v[b].x += comb.x; v[b].y += comb.y; v[b].z += comb.z; v[b].w += comb.w;
        __stcs(&out[row + (size_t)b * bstride], v[b]);
    }
}

extern "C" void kernel_launch(void* const* d_in, const int* in_sizes, int n_in,
                              void* d_out, int out_size)
{
    const float* x        = (const float*)d_in[0];
    const float* pix_pe   = (const float*)d_in[1];
    const float* grd_pe   = (const float*)d_in[2];
    const float* pr_pe    = (const float*)d_in[3];
    const int*   g_starts = (const int*)d_in[4];
    const int*   g_lens   = (const int*)d_in[5];
    const int*   p_starts = (const int*)d_in[6];
    const int*   p_lens   = (const int*)d_in[7];

    const int D = in_sizes[2] / 2;            // grids_pe is [2, D]
    const int n_grids = in_sizes[4];
    const int n_pairs = in_sizes[6];
    const int n_pairs_pe_rows = in_sizes[3] / D;
    const int S = out_size / (B_CONST * D);   // 16384

    pe_add_kernel<<<S, 128>>>(
        (const float4*)x, (const float4*)pix_pe, (const float4*)grd_pe, (const float4*)pr_pe,
        g_starts, g_lens, p_starts, p_lens,
        n_grids, n_pairs, n_pairs_pe_rows, S,
        (float4*)d_out);
}